// round 15
// baseline (speedup 1.0000x reference)
#include <cuda_runtime.h>
#include <cuda_bf16.h>
#include <cuda_fp16.h>
#include <cstdint>
#include <math.h>

#define VIEW 8
#define SEQ  2048
#define HID  1024
#define ATT  128
#define SCALE 0.08838834764831845f   // ATT^-0.5

// ======================= device scratch (no allocs allowed) =================
__device__ __align__(256) __half g_wqT_h[ATT*HID], g_wqT_l[ATT*HID];
__device__ __align__(256) __half g_wkT_h[ATT*HID], g_wkT_l[ATT*HID];
__device__ __align__(256) __half g_wvT_h[ATT*HID], g_wvT_l[ATT*HID];
__device__ __align__(256) __half g_woT_h[HID*HID], g_woT_l[HID*HID];
__device__ __align__(256) __half g_qh[VIEW*SEQ*ATT];
__device__ __align__(256) __half g_kh[VIEW*SEQ*ATT];
__device__ __align__(256) __half g_vh[VIEW*SEQ*ATT];
__device__ __align__(256) float g_x_bias[VIEW*SEQ*ATT];
__device__ __align__(256) __half g_x[VIEW*SEQ*ATT];

// ======================= helpers ===========================================
__device__ __forceinline__ uint32_t smem_u32(const void* p) {
    uint32_t a;
    asm("{ .reg .u64 t; cvta.to.shared.u64 t, %1; cvt.u32.u64 %0, t; }" : "=r"(a) : "l"(p));
    return a;
}
__device__ __forceinline__ void split2h(float x, __half& h, __half& l) {
    h = __float2half_rn(x);
    l = __float2half_rn(x - __half2float(h));
}

#define CP_ASYNC16(saddr, gptr) \
    asm volatile("cp.async.cg.shared.global [%0], [%1], 16;" \
                 :: "r"(saddr), "l"(__cvta_generic_to_global(gptr)) : "memory")
#define CP_COMMIT() asm volatile("cp.async.commit_group;" ::: "memory")
#define CP_WAIT0()  asm volatile("cp.async.wait_group 0;" ::: "memory")
#define CP_WAIT1()  asm volatile("cp.async.wait_group 1;" ::: "memory")

#define LDSM4(R, addr) \
    asm volatile("ldmatrix.sync.aligned.m8n8.x4.shared.b16 {%0,%1,%2,%3}, [%4];" \
                 : "=r"((R)[0]), "=r"((R)[1]), "=r"((R)[2]), "=r"((R)[3]) : "r"(addr))
#define LDSM4T(R, addr) \
    asm volatile("ldmatrix.sync.aligned.m8n8.x4.trans.shared.b16 {%0,%1,%2,%3}, [%4];" \
                 : "=r"((R)[0]), "=r"((R)[1]), "=r"((R)[2]), "=r"((R)[3]) : "r"(addr))

#define MMA16816F(C, A, b0, b1) \
    asm volatile("mma.sync.aligned.m16n8k16.row.col.f32.f16.f16.f32 " \
                 "{%0,%1,%2,%3},{%4,%5,%6,%7},{%8,%9},{%0,%1,%2,%3};" \
                 : "+f"((C)[0]), "+f"((C)[1]), "+f"((C)[2]), "+f"((C)[3]) \
                 : "r"((A)[0]), "r"((A)[1]), "r"((A)[2]), "r"((A)[3]), "r"(b0), "r"(b1))

// ======================= fused weight transpose+split (fp16 h/l) ===========
__global__ void transpose_split_w_all(const float* __restrict__ wq,
                                      const float* __restrict__ wk,
                                      const float* __restrict__ wv,
                                      const float* __restrict__ wo) {
    const int mode = blockIdx.z;
    const float* in;
    __half *dh, *dl; int C;
    if (mode == 0)      { in = wq; dh = g_wqT_h; dl = g_wqT_l; C = ATT; }
    else if (mode == 1) { in = wk; dh = g_wkT_h; dl = g_wkT_l; C = ATT; }
    else if (mode == 2) { in = wv; dh = g_wvT_h; dl = g_wvT_l; C = ATT; }
    else                { in = wo; dh = g_woT_h; dl = g_woT_l; C = HID; }
    if ((int)blockIdx.x * 32 >= C) return;
    __shared__ float t[32][33];
    const int R = HID;
    int c0 = blockIdx.x * 32, r0 = blockIdx.y * 32;
    int tx = threadIdx.x, ty = threadIdx.y;
#pragma unroll
    for (int i = 0; i < 4; i++)
        t[ty + i*8][tx] = in[(size_t)(r0 + ty + i*8) * C + c0 + tx];
    __syncthreads();
#pragma unroll
    for (int i = 0; i < 4; i++) {
        float x = t[tx][ty + i*8];
        __half h, l; split2h(x, h, l);
        size_t o = (size_t)(c0 + ty + i*8) * R + r0 + tx;
        dh[o] = h; dl[o] = l;
    }
}

// ======================= swizzles ==========================================
__device__ __forceinline__ uint32_t swz(int row, int chunk) {       // 64B rows
    return (uint32_t)(row * 64 + ((chunk ^ ((row >> 1) & 3)) * 16));
}
__device__ __forceinline__ uint32_t swz256(int row, int chunk) {    // 256B rows
    return (uint32_t)(row * 256 + ((chunk ^ (row & 7)) * 16));
}
__device__ __forceinline__ uint32_t swz128(int row, int chunk) {    // 128B rows
    return (uint32_t)(row * 128 + ((chunk ^ (row & 7)) * 16));
}

// ======================= GEMM template =====================================
#define GT 256
#define KC 32

template <int ROWS>
__device__ __forceinline__ void load_tile_async(uint32_t sbase,
                                                const __half* __restrict__ src,
                                                size_t row0, size_t ld) {
    int t = threadIdx.x;
#pragma unroll
    for (int i = 0; i < ROWS / 64; i++) {
        int id = t + i * 256;
        int row = id >> 2, c = id & 3;
        CP_ASYNC16(sbase + swz(row, c), src + (row0 + row) * ld + c * 8);
    }
}
__device__ __forceinline__ void load_vtile_async(uint32_t sbase,
                                                 const __half* __restrict__ src,
                                                 size_t row0) {
    int t = threadIdx.x;
#pragma unroll
    for (int i = 0; i < 2; i++) {
        int id = t + i * 256;
        int row = id >> 4, c = id & 15;
        CP_ASYNC16(sbase + swz256(row, c), src + (row0 + row) * ATT + c * 8);
    }
}
template <int ROWS>
__device__ __forceinline__ void load_fp_async(uint32_t sbase,
                                              const float* __restrict__ src,
                                              size_t row0, size_t ld) {
    int t = threadIdx.x;
#pragma unroll
    for (int i = 0; i < ROWS / 32; i++) {
        int id = t + i * 256;
        int row = id >> 3, c = id & 7;
        CP_ASYNC16(sbase + swz128(row, c), src + (row0 + row) * ld + c * 4);
    }
}

// STAGE 0: proj (MT=128)  A = fp32 input -> fp16, B wT fp16 single, K=1024
// STAGE 2: biasv (MT=64)  A = fp32 attn_bias -> fp16, B vh fp16 single (trans), K=2048
// STAGE 3: outproj (MT=64) A = g_x fp16, B woT fp16 h/l, K=1024
template <int STAGE>
__global__ __launch_bounds__(GT, 2)
void gemm_kernel(const float* __restrict__ i0, const float* __restrict__ i1,
                 const float* __restrict__ i2, const float* __restrict__ b0,
                 const float* __restrict__ b1, const float* __restrict__ b2,
                 float* __restrict__ pout, int zbase) {
    constexpr int MT  = (STAGE == 0) ? 128 : 64;
    constexpr int MTI = MT / 32;
    constexpr bool FPA = (STAGE == 0 || STAGE == 2);
    constexpr bool BSINGLE = (STAGE == 0 || STAGE == 2);
    constexpr uint32_t A_T  = MT * 64;
    constexpr uint32_t FPB  = MT * 128;
    constexpr uint32_t AH_OFF = FPA ? 2 * FPB : 0;
    constexpr uint32_t B_OFF  = FPA ? (2 * FPB + A_T) : (2 * A_T);
    constexpr uint32_t B_STRIDE = BSINGLE ? 8192u : 16384u;

    extern __shared__ char smem[];
    const uint32_t sb = smem_u32(smem);
    const int tid = threadIdx.x, wid = tid >> 5, lane = tid & 31;
    const int wm = wid & 1, wn = wid >> 1;

    const __half *Bh0 = nullptr, *Bl0 = nullptr;
    const float* Xf = nullptr;
    size_t ldA = 0, ldB = 0, rowA0 = 0, rowB0 = 0;
    int K_TOTAL = 0;
    if constexpr (STAGE == 0) {
        int z = blockIdx.z + zbase;
        Xf  = z == 0 ? i0 : z == 1 ? i1 : i2;
        Bh0 = z == 0 ? g_wqT_h : z == 1 ? g_wkT_h : g_wvT_h;
        ldA = HID; ldB = HID; rowA0 = (size_t)blockIdx.x * MT; K_TOTAL = HID;
    } else if constexpr (STAGE == 2) {
        size_t z = blockIdx.z;
        Xf  = i0 + z * (size_t)SEQ * SEQ;
        Bh0 = g_vh + z * (size_t)SEQ * ATT;
        ldA = SEQ;
        rowA0 = (size_t)blockIdx.x * MT; K_TOTAL = SEQ;
    } else {
        Bh0 = g_woT_h; Bl0 = g_woT_l;
        ldA = ATT; ldB = HID;
        rowA0 = (size_t)blockIdx.x * MT; rowB0 = (size_t)blockIdx.y * 128; K_TOTAL = HID;
    }
    const int nc = K_TOTAL / KC;

    auto load_chunk = [&](int c, int buf) {
        const int kb = c * KC;
        if constexpr (FPA) {
            load_fp_async<MT>(sb + buf * FPB, Xf + kb, rowA0, ldA);
        } else {
            size_t voff = (size_t)(kb >> 7) * (SEQ * ATT) + (kb & 127);
            load_tile_async<MT>(sb + buf * A_T, g_x + voff, rowA0, ldA);
        }
        if constexpr (STAGE == 2) {
            load_vtile_async(sb + B_OFF + buf * B_STRIDE, Bh0, (size_t)kb);
        } else if constexpr (STAGE == 0) {
            load_tile_async<128>(sb + B_OFF + buf * B_STRIDE, Bh0 + kb, rowB0, ldB);
        } else {
            load_tile_async<128>(sb + B_OFF + buf * B_STRIDE,        Bh0 + kb, rowB0, ldB);
            load_tile_async<128>(sb + B_OFF + buf * B_STRIDE + 8192, Bl0 + kb, rowB0, ldB);
        }
    };

    float acc[MTI][4][4];
#pragma unroll
    for (int a = 0; a < MTI; a++)
#pragma unroll
        for (int b = 0; b < 4; b++)
#pragma unroll
            for (int r2 = 0; r2 < 4; r2++) acc[a][b][r2] = 0.f;

    const int j8 = lane >> 3, r8 = lane & 7;
    const int aRowB = wm * (MT / 2) + (j8 & 1) * 8 + r8;
    const int aChB  = (j8 >> 1);
    const int bRowB = wn * 32 + (j8 >> 1) * 8 + r8;
    const int bChB  = (j8 & 1);
    const int vRowB = (j8 & 1) * 8 + r8;
    const int vChB  = wn * 4 + (j8 >> 1);

    load_chunk(0, 0);
    CP_COMMIT();

    for (int c = 0; c < nc; c++) {
        if (c + 1 < nc) {
            load_chunk(c + 1, (c + 1) & 1);
            CP_COMMIT();
            CP_WAIT1();
        } else {
            CP_WAIT0();
        }
        __syncthreads();

        if constexpr (FPA) {
            const char* fpb = smem + (c & 1) * FPB;
#pragma unroll
            for (int i = 0; i < MT / 64; i++) {
                int id = tid + i * 256;
                const int row = id >> 2, q = id & 3;
                float4 f0 = *reinterpret_cast<const float4*>(fpb + swz128(row, q * 2));
                float4 f1 = *reinterpret_cast<const float4*>(fpb + swz128(row, q * 2 + 1));
                __half2 p0 = __floats2half2_rn(f0.x, f0.y);
                __half2 p1 = __floats2half2_rn(f0.z, f0.w);
                __half2 p2 = __floats2half2_rn(f1.x, f1.y);
                __half2 p3 = __floats2half2_rn(f1.z, f1.w);
                uint4 hh;
                hh.x = *reinterpret_cast<uint32_t*>(&p0);
                hh.y = *reinterpret_cast<uint32_t*>(&p1);
                hh.z = *reinterpret_cast<uint32_t*>(&p2);
                hh.w = *reinterpret_cast<uint32_t*>(&p3);
                *reinterpret_cast<uint4*>(smem + AH_OFF + swz(row, q)) = hh;
            }
            __syncthreads();
        }

        const uint32_t aB = FPA ? sb + AH_OFF : sb + (c & 1) * A_T;
        const uint32_t bB = sb + B_OFF + (c & 1) * B_STRIDE;
        const uint32_t blB = bB + 8192;
#pragma unroll
        for (int s = 0; s < 2; s++) {
            const int c0 = 2 * s;
            uint32_t ah[MTI][4], bh[2][4], bl[2][4];
#pragma unroll
            for (int mt = 0; mt < MTI; mt++)
                LDSM4(ah[mt], aB + swz(aRowB + mt * 16, aChB + c0));
#pragma unroll
            for (int g = 0; g < 2; g++) {
                if constexpr (STAGE == 2) {
                    LDSM4T(bh[g], bB + swz256(s * 16 + vRowB, vChB + g * 2));
                } else if constexpr (STAGE == 0) {
                    LDSM4(bh[g], bB + swz(bRowB + g * 16, bChB + c0));
                } else {
                    LDSM4(bh[g], bB  + swz(bRowB + g * 16, bChB + c0));
                    LDSM4(bl[g], blB + swz(bRowB + g * 16, bChB + c0));
                }
            }
#pragma unroll
            for (int mt = 0; mt < MTI; mt++)
#pragma unroll
                for (int nt = 0; nt < 4; nt++) {
                    const int g = nt >> 1, p = (nt & 1) * 2;
                    MMA16816F(acc[mt][nt], ah[mt], bh[g][p], bh[g][p + 1]);
                    if constexpr (!BSINGLE)
                        MMA16816F(acc[mt][nt], ah[mt], bl[g][p], bl[g][p + 1]);
                }
        }
        __syncthreads();
    }

    const int gid = lane >> 2, tig = lane & 3;
#pragma unroll
    for (int mt = 0; mt < MTI; mt++) {
#pragma unroll
        for (int h = 0; h < 2; h++) {
            const int m = (int)(blockIdx.x * MT) + wm * (MT / 2) + mt * 16 + gid + h * 8;
#pragma unroll
            for (int nt = 0; nt < 4; nt++) {
                const int n = wn * 32 + nt * 8 + tig * 2;
                float v0 = acc[mt][nt][h * 2];
                float v1 = acc[mt][nt][h * 2 + 1];
                if constexpr (STAGE == 0) {
                    int z = blockIdx.z + zbase;
                    const float* bias = z == 0 ? b0 : z == 1 ? b1 : b2;
                    float scl = (z == 0) ? SCALE : 1.f;
                    v0 = (v0 + bias[n]) * scl; v1 = (v1 + bias[n + 1]) * scl;
                    size_t o = (size_t)m * ATT + n;
                    __half* dst = z == 0 ? g_qh : z == 1 ? g_kh : g_vh;
                    __half2 hh = __floats2half2_rn(v0, v1);
                    *reinterpret_cast<__half2*>(dst + o) = hh;
                } else if constexpr (STAGE == 2) {
                    size_t z = blockIdx.z;
                    float2 w; w.x = v0; w.y = v1;
                    *reinterpret_cast<float2*>(g_x_bias + (z * SEQ + m) * (size_t)ATT + n) = w;
                } else {
                    const int ng = (int)(blockIdx.y * 128) + n;
                    float2 w; w.x = v0 + b0[ng]; w.y = v1 + b0[ng + 1];
                    *reinterpret_cast<float2*>(pout + (size_t)m * HID + ng) = w;
                }
            }
        }
    }
}

// ======================= flash attention (1024 thr, 32 warps, 8x4 grid) ====
#define FL_QH 0u
#define FL_KB 32768u
#define FL_PH 163840u
#define FL_RS 196608u
#define FL_SMEM 198656

__global__ __launch_bounds__(1024, 1) void flash_kernel() {
    extern __shared__ char smem[];
    const uint32_t sb = smem_u32(smem);
    const int tid = threadIdx.x, wid = tid >> 5, lane = tid & 31;
    const int wm = wid & 7, wn = wid >> 3;      // 8 (M, 16q each) x 4 (N, 32k/32a bands)
    const size_t z = blockIdx.z;
    const size_t q0 = (size_t)blockIdx.x * 128;

    const __half* Qs = g_qh + z * SEQ * ATT;
    const __half* Ks = g_kh + z * SEQ * ATT;
    const __half* Vs = g_vh + z * SEQ * ATT;

    {
        int t = tid;
#pragma unroll
        for (int i = 0; i < 2; i++) {
            int id = t + i * 1024;
            int row = id >> 4, c = id & 15;
            CP_ASYNC16(sb + FL_QH + swz256(row, c), Qs + (q0 + row) * ATT + c * 8);
        }
    }
    // buffers: buf*65536: K @ FL_KB + buf*65536, V @ +32768
    auto loadKV = [&](int kt, int buf) {
        const size_t r0 = (size_t)kt * 128;
        const uint32_t kb = sb + FL_KB + buf * 65536u;
        const uint32_t vb = kb + 32768u;
        int t = tid;
#pragma unroll
        for (int i = 0; i < 2; i++) {
            int id = t + i * 1024;
            int row = id >> 4, c = id & 15;
            CP_ASYNC16(kb + swz256(row, c), Ks + (r0 + row) * ATT + c * 8);
            CP_ASYNC16(vb + swz256(row, c), Vs + (r0 + row) * ATT + c * 8);
        }
    };
    loadKV(0, 0);
    CP_COMMIT();

    float U[4][4];
#pragma unroll
    for (int b = 0; b < 4; b++)
#pragma unroll
        for (int r = 0; r < 4; r++) U[b][r] = 0.f;
    float rsum[2];
    rsum[0] = 0.f; rsum[1] = 0.f;

    const int j8 = lane >> 3, r8 = lane & 7;
    const int aRow = wm * 16 + (j8 & 1) * 8 + r8;   // Q / P A-frag rows (16 per warp)
    const int aCh  = (j8 >> 1);
    const int kRowB = wn * 32 + (j8 >> 1) * 8 + r8; // K as B: 32-key band, + g*16
    const int kCh  = (j8 & 1);
    const int vRow = (j8 & 1) * 8 + r8;             // V trans B: + ks2*16
    const int vCh  = wn * 4 + (j8 >> 1);            // a-band wn*32, + g*2
    const int gid = lane >> 2, tig = lane & 3;

    for (int kt = 0; kt < 16; kt++) {
        CP_WAIT0();
        __syncthreads();
        if (kt + 1 < 16) { loadKV(kt + 1, (kt + 1) & 1); CP_COMMIT(); }

        const uint32_t kb = sb + FL_KB + (kt & 1) * 65536u;
        float sacc[4][4];
#pragma unroll
        for (int b = 0; b < 4; b++)
#pragma unroll
            for (int r = 0; r < 4; r++) sacc[b][r] = 0.f;
#pragma unroll
        for (int ks = 0; ks < 8; ks++) {
            uint32_t qa[4], kf[2][4];
            LDSM4(qa, sb + FL_QH + swz256(aRow, ks * 2 + aCh));
#pragma unroll
            for (int g = 0; g < 2; g++)
                LDSM4(kf[g], kb + swz256(kRowB + g * 16, ks * 2 + kCh));
#pragma unroll
            for (int nt = 0; nt < 4; nt++) {
                const int g = nt >> 1, p = (nt & 1) * 2;
                MMA16816F(sacc[nt], qa, kf[g][p], kf[g][p + 1]);
            }
        }
        // P = exp(S) -> fp16, store band to P smem (256B rows), rowsums
#pragma unroll
        for (int nt = 0; nt < 4; nt++) {
            float e0 = __expf(sacc[nt][0]);
            float e1 = __expf(sacc[nt][1]);
            float e2 = __expf(sacc[nt][2]);
            float e3 = __expf(sacc[nt][3]);
            rsum[0] += e0 + e1;
            rsum[1] += e2 + e3;
            __half2 p01 = __floats2half2_rn(e0, e1);
            __half2 p23 = __floats2half2_rn(e2, e3);
            const int rlo = wm * 16 + gid;
            const int chunk = wn * 4 + nt;
            uint32_t oflo = (uint32_t)(rlo * 256 + ((chunk ^ (rlo & 7)) * 16) + tig * 4);
            const int rhi = rlo + 8;
            uint32_t ofhi = (uint32_t)(rhi * 256 + ((chunk ^ (rhi & 7)) * 16) + tig * 4);
            *reinterpret_cast<uint32_t*>(smem + FL_PH + oflo) = *reinterpret_cast<uint32_t*>(&p01);
            *reinterpret_cast<uint32_t*>(smem + FL_PH + ofhi) = *reinterpret_cast<uint32_t*>(&p23);
        }
        __syncthreads();
        const uint32_t vb = kb + 32768u;
#pragma unroll
        for (int ks2 = 0; ks2 < 8; ks2++) {
            uint32_t pa[4], vh_[2][4];
            LDSM4(pa, sb + FL_PH + swz256(aRow, ks2 * 2 + aCh));
#pragma unroll
            for (int g = 0; g < 2; g++)
                LDSM4T(vh_[g], vb + swz256(ks2 * 16 + vRow, vCh + g * 2));
#pragma unroll
            for (int nt = 0; nt < 4; nt++) {
                const int g = nt >> 1, p = (nt & 1) * 2;
                MMA16816F(U[nt], pa, vh_[g][p], vh_[g][p + 1]);
            }
        }
    }
    __syncthreads();

    float* rs = reinterpret_cast<float*>(smem + FL_RS);   // [128][4]
#pragma unroll
    for (int h = 0; h < 2; h++) {
        float s = rsum[h];
        s += __shfl_xor_sync(0xffffffffu, s, 1);
        s += __shfl_xor_sync(0xffffffffu, s, 2);
        rsum[h] = s;
    }
    if (tig == 0) {
#pragma unroll
        for (int h = 0; h < 2; h++) {
            int row = wm * 16 + gid + h * 8;
            rs[row * 4 + wn] = rsum[h];
        }
    }
    __syncthreads();

#pragma unroll
    for (int h = 0; h < 2; h++) {
        const int rowL = wm * 16 + gid + h * 8;
        const float tot = rs[rowL * 4 + 0] + rs[rowL * 4 + 1]
                        + rs[rowL * 4 + 2] + rs[rowL * 4 + 3];
        const float inv = 1.f / tot;
        const size_t m = q0 + rowL;
#pragma unroll
        for (int nt = 0; nt < 4; nt++) {
            const int n = wn * 32 + nt * 8 + tig * 2;
            const size_t o = (z * SEQ + m) * (size_t)ATT + n;
            float2 xb = *reinterpret_cast<const float2*>(g_x_bias + o);
            float v0 = U[nt][h * 2]     * inv + xb.x;
            float v1 = U[nt][h * 2 + 1] * inv + xb.y;
            __half2 hh = __floats2half2_rn(v0, v1);
            *reinterpret_cast<__half2*>(g_x + o) = hh;
        }
    }
}

// ======================= launch ============================================
extern "C" void kernel_launch(void* const* d_in, const int* in_sizes, int n_in,
                              void* d_out, int out_size) {
    const float* q         = (const float*)d_in[0];
    const float* k         = (const float*)d_in[1];
    const float* v         = (const float*)d_in[2];
    const float* attn_bias = (const float*)d_in[3];
    const float* wq        = (const float*)d_in[4];
    const float* bq        = (const float*)d_in[5];
    const float* wk        = (const float*)d_in[6];
    const float* bk        = (const float*)d_in[7];
    const float* wv        = (const float*)d_in[8];
    const float* bv        = (const float*)d_in[9];
    const float* wo        = (const float*)d_in[10];
    const float* bo        = (const float*)d_in[11];
    float* out = (float*)d_out;

    static bool s_init = false;
    static cudaStream_t s2;
    static cudaEvent_t evT, ev2;
    if (!s_init) {
        s_init = true;
        cudaStreamCreateWithFlags(&s2, cudaStreamNonBlocking);
        cudaEventCreateWithFlags(&evT, cudaEventDisableTiming);
        cudaEventCreateWithFlags(&ev2, cudaEventDisableTiming);
        cudaFuncSetAttribute(gemm_kernel<0>, cudaFuncAttributeMaxDynamicSharedMemorySize, 57344);
        cudaFuncSetAttribute(gemm_kernel<2>, cudaFuncAttributeMaxDynamicSharedMemorySize, 36864);
        cudaFuncSetAttribute(gemm_kernel<3>, cudaFuncAttributeMaxDynamicSharedMemorySize, 40960);
        cudaFuncSetAttribute(flash_kernel,   cudaFuncAttributeMaxDynamicSharedMemorySize, FL_SMEM);
    }

    // 1) weights -> wT fp16 hi/lo
    transpose_split_w_all<<<dim3(32, 32, 4), dim3(32, 8)>>>(wq, wk, wv, wo);
    cudaEventRecord(evT, 0);
    cudaStreamWaitEvent(s2, evT, 0);

    // side stream: v-projection then bias@vh
    gemm_kernel<0><<<dim3(VIEW * SEQ / 128, 1, 1), GT, 57344, s2>>>(
        q, k, v, bq, bk, bv, nullptr, 2);
    gemm_kernel<2><<<dim3(SEQ / 64, 1, VIEW), GT, 36864, s2>>>(
        attn_bias, nullptr, nullptr, nullptr, nullptr, nullptr, nullptr, 0);
    cudaEventRecord(ev2, s2);

    // main stream: q,k projections
    gemm_kernel<0><<<dim3(VIEW * SEQ / 128, 1, 2), GT, 57344>>>(
        q, k, v, bq, bk, bv, nullptr, 0);

    cudaStreamWaitEvent(0, ev2, 0);
    // 4) flash (1024 threads, 32 warps)
    flash_kernel<<<dim3(SEQ / 128, 1, VIEW), 1024, FL_SMEM>>>();
    // 5) output projection
    gemm_kernel<3><<<dim3(SEQ / 64, HID / 128), GT, 40960>>>(
        nullptr, nullptr, nullptr, bo, nullptr, nullptr, out, 0);
}